// round 2
// baseline (speedup 1.0000x reference)
#include <cuda_runtime.h>
#include <math.h>

#define NN 100000
#define NE 1600000
#define DIN 128
#define DH 64

// Scratch (allocation-free: __device__ globals)
__device__ float g_bufA[NN * DH];
__device__ float g_bufB[NN * DH];
__device__ float g_deg[NN];
__device__ float g_dinv[NN];
__device__ float g_w[NE];

// ---------------- degree / edge-weight prep ----------------

__global__ void k_deg_init() {
    int i = blockIdx.x * blockDim.x + threadIdx.x;
    if (i < NN) g_deg[i] = 1.0f;  // self-loop
}

__global__ void k_deg_accum(const int* __restrict__ dst) {
    int e = blockIdx.x * blockDim.x + threadIdx.x;
    if (e < NE) atomicAdd(&g_deg[dst[e]], 1.0f);
}

__global__ void k_dinv() {
    int i = blockIdx.x * blockDim.x + threadIdx.x;
    if (i < NN) g_dinv[i] = rsqrtf(g_deg[i]);
}

__global__ void k_edge_w(const int* __restrict__ src, const int* __restrict__ dst) {
    int e = blockIdx.x * blockDim.x + threadIdx.x;
    if (e < NE) g_w[e] = g_dinv[src[e]] * g_dinv[dst[e]];
}

// ---------------- GEMM: H[n,64] = X[n,K] @ W[64,K]^T + b ----------------
// W stored transposed in smem (sW[k*64+j]) -> conflict-free inner loads.

template <int K>
__global__ void k_gemm(const float* __restrict__ X, const float* __restrict__ W,
                       const float* __restrict__ B, float* __restrict__ H) {
    __shared__ float sW[K * DH];   // transposed: sW[k*64 + j]
    __shared__ float sX[4][K];
    int tid = threadIdx.x;

    for (int i = tid; i < DH * K; i += 256) {
        int j = i / K, k = i % K;
        sW[k * DH + j] = W[i];
    }
    int j = tid & 63;
    int r = tid >> 6;
    float bias = B[j];
    int base = blockIdx.x * 64;

    for (int g = 0; g < 16; g++) {
        __syncthreads();
        int n0 = base + g * 4;
        for (int i = tid; i < 4 * K; i += 256) {
            int nn = n0 + i / K;
            sX[i / K][i % K] = (nn < NN) ? X[(size_t)nn * K + (i % K)] : 0.0f;
        }
        __syncthreads();
        int node = n0 + r;
        if (node < NN) {
            float acc = bias;
#pragma unroll
            for (int k = 0; k < K; k++)
                acc = fmaf(sX[r][k], sW[k * DH + j], acc);
            H[(size_t)node * DH + j] = acc;
        }
    }
}

// ---------------- propagation ----------------

// agg = h * dinv^2 (self-loop contribution), initializes the accumulator
__global__ void k_agg_init(const float* __restrict__ h, float* __restrict__ agg) {
    int i = blockIdx.x * blockDim.x + threadIdx.x;
    if (i < NN * DH) {
        float di = g_dinv[i >> 6];
        agg[i] = h[i] * di * di;
    }
}

// vectorized global reduction: one 16B atomic add instead of 4 scalar ones
__device__ __forceinline__ void red_add_v4(float* p, float a, float b, float c, float d) {
    asm volatile("red.global.add.v4.f32 [%0], {%1, %2, %3, %4};"
                 :: "l"(p), "f"(a), "f"(b), "f"(c), "f"(d) : "memory");
}

// agg[dst] += w * h[src]   (16 threads per edge, one red.v4 each)
__global__ void k_prop(const int* __restrict__ src, const int* __restrict__ dst,
                       const float* __restrict__ h, float* agg) {
    int idx = blockIdx.x * blockDim.x + threadIdx.x;
    int e = idx >> 4;
    if (e >= NE) return;
    int c = (idx & 15) << 2;
    int s = src[e];
    int d = dst[e];
    float w = g_w[e];
    float4 v = *(const float4*)(h + (size_t)s * DH + c);
    float* o = agg + (size_t)d * DH + c;
    red_add_v4(o, v.x * w, v.y * w, v.z * w, v.w * w);
}

// out = relu(l2norm(0.5*h + 0.5*agg)); one warp per node, float2 per lane
__global__ void k_post(const float* __restrict__ h, const float* __restrict__ agg,
                       float* out) {
    int node = blockIdx.x * 8 + (threadIdx.x >> 5);
    int lane = threadIdx.x & 31;
    if (node >= NN) return;
    const float2* hp = (const float2*)(h + (size_t)node * DH);
    const float2* ap = (const float2*)(agg + (size_t)node * DH);
    float2 a = hp[lane];
    float2 g = ap[lane];
    float vx = 0.5f * (a.x + g.x);
    float vy = 0.5f * (a.y + g.y);
    float s = vx * vx + vy * vy;
#pragma unroll
    for (int o = 16; o; o >>= 1) s += __shfl_xor_sync(0xFFFFFFFFu, s, o);
    float inv = 1.0f / fmaxf(sqrtf(s), 1e-12f);
    float2 o2;
    o2.x = fmaxf(vx * inv, 0.0f);
    o2.y = fmaxf(vy * inv, 0.0f);
    ((float2*)(out + (size_t)node * DH))[lane] = o2;
}

// ---------------- launch ----------------

extern "C" void kernel_launch(void* const* d_in, const int* in_sizes, int n_in,
                              void* d_out, int out_size) {
    const float* x  = (const float*)d_in[0];
    const int*   ei = (const int*)d_in[1];
    const float* W0 = (const float*)d_in[2];
    const float* b0 = (const float*)d_in[3];
    const float* W1 = (const float*)d_in[4];
    const float* b1 = (const float*)d_in[5];
    const float* W2 = (const float*)d_in[6];
    const float* b2 = (const float*)d_in[7];
    float* out = (float*)d_out;

    const int* src = ei;
    const int* dst = ei + NE;

    float *pA, *pB;
    cudaGetSymbolAddress((void**)&pA, g_bufA);
    cudaGetSymbolAddress((void**)&pB, g_bufB);

    const int T = 256;
    int gN  = (NN + T - 1) / T;
    int gE  = (NE + T - 1) / T;
    int gNH = (NN * DH + T - 1) / T;
    int gP  = (NE * 16 + T - 1) / T;
    int gG  = (NN + 63) / 64;
    int gPost = (NN + 7) / 8;

    // edge weights (recomputed each call: deterministic, no caching)
    k_deg_init<<<gN, T>>>();
    k_deg_accum<<<gE, T>>>(dst);
    k_dinv<<<gN, T>>>();
    k_edge_w<<<gE, T>>>(src, dst);

    // layer 0
    k_gemm<DIN><<<gG, T>>>(x, W0, b0, pA);
    k_agg_init<<<gNH, T>>>(pA, pB);
    k_prop<<<gP, T>>>(src, dst, pA, pB);
    k_post<<<gPost, T>>>(pA, pB, pA);

    // layer 1
    k_gemm<DH><<<gG, T>>>(pA, W1, b1, pB);
    k_agg_init<<<gNH, T>>>(pB, pA);
    k_prop<<<gP, T>>>(src, dst, pB, pA);
    k_post<<<gPost, T>>>(pB, pA, pB);

    // final linear
    k_gemm<DH><<<gG, T>>>(pB, W2, b2, out);
}

// round 3
// speedup vs baseline: 1.1356x; 1.1356x over previous
#include <cuda_runtime.h>
#include <math.h>

#define NN 100000
#define NE 1600000
#define DIN 128
#define DH 64

// Scratch (allocation-free: __device__ globals)
__device__ float g_bufA[NN * DH];
__device__ float g_bufB[NN * DH];
__device__ float g_deg[NN];
__device__ float g_dinv[NN];

// ---------------- degree prep ----------------

__global__ void k_deg_init() {
    int i = blockIdx.x * blockDim.x + threadIdx.x;
    if (i < NN) g_deg[i] = 1.0f;  // self-loop
}

__global__ void k_deg_accum(const int* __restrict__ dst) {
    int e = blockIdx.x * blockDim.x + threadIdx.x;
    if (e < NE) atomicAdd(&g_deg[dst[e]], 1.0f);
}

__global__ void k_dinv() {
    int i = blockIdx.x * blockDim.x + threadIdx.x;
    if (i < NN) g_dinv[i] = rsqrtf(g_deg[i]);
}

// ---------------- GEMM: H[n,64] = X[n,K] @ W[64,K]^T + b ----------------
// Register microtile: each thread -> 1 node x 4 output cols.
// Per k: 1 broadcast LDS (x) + 1 LDS.128 (w) + 4 FMA.

template <int K>
__global__ void __launch_bounds__(256) k_gemm(const float* __restrict__ X,
                                              const float* __restrict__ W,
                                              const float* __restrict__ B,
                                              float* __restrict__ H) {
    __shared__ float sW[K * DH];        // transposed: sW[k*64 + j]
    __shared__ float sX[16][K + 1];     // +1 pad: no bank conflict on broadcast pair
    int tid = threadIdx.x;

    for (int i = tid; i < DH * K; i += 256) {
        int j = i / K, k = i % K;
        sW[k * DH + j] = W[i];
    }
    int c  = tid & 15;       // col group -> cols [4c, 4c+3]
    int rr = tid >> 4;       // node within group of 16
    int j0 = c * 4;
    float4 bias = *(const float4*)(B + j0);
    int base = blockIdx.x * 64;

    for (int g = 0; g < 4; g++) {
        __syncthreads();
        int n0 = base + g * 16;
        for (int i = tid; i < 16 * K; i += 256) {
            int nn = n0 + i / K;
            sX[i / K][i % K] = (nn < NN) ? X[(size_t)nn * K + (i % K)] : 0.0f;
        }
        __syncthreads();
        int node = n0 + rr;
        if (node < NN) {
            float a0 = bias.x, a1 = bias.y, a2 = bias.z, a3 = bias.w;
#pragma unroll 16
            for (int k = 0; k < K; k++) {
                float xv = sX[rr][k];
                float4 w = *(const float4*)(sW + k * DH + j0);
                a0 = fmaf(xv, w.x, a0);
                a1 = fmaf(xv, w.y, a1);
                a2 = fmaf(xv, w.z, a2);
                a3 = fmaf(xv, w.w, a3);
            }
            *(float4*)(H + (size_t)node * DH + j0) = make_float4(a0, a1, a2, a3);
        }
    }
}

// ---------------- propagation ----------------

// zero the accumulator (write-only; self-loop folded into k_post)
__global__ void k_zero(float* __restrict__ agg) {
    int i = blockIdx.x * blockDim.x + threadIdx.x;
    if (i < NN * DH / 4) ((float4*)agg)[i] = make_float4(0.f, 0.f, 0.f, 0.f);
}

// vectorized global reduction: one 16B atomic add instead of 4 scalar ones
__device__ __forceinline__ void red_add_v4(float* p, float a, float b, float c, float d) {
    asm volatile("red.global.add.v4.f32 [%0], {%1, %2, %3, %4};"
                 :: "l"(p), "f"(a), "f"(b), "f"(c), "f"(d) : "memory");
}

// agg[dst] += dinv[src]*dinv[dst] * h[src]   (16 threads per edge, one red.v4 each)
__global__ void k_prop(const int* __restrict__ src, const int* __restrict__ dst,
                       const float* __restrict__ h, float* agg) {
    int idx = blockIdx.x * blockDim.x + threadIdx.x;
    int e = idx >> 4;
    if (e >= NE) return;
    int c = (idx & 15) << 2;
    int s = src[e];
    int d = dst[e];
    float w = g_dinv[s] * g_dinv[d];
    float4 v = *(const float4*)(h + (size_t)s * DH + c);
    float* o = agg + (size_t)d * DH + c;
    red_add_v4(o, v.x * w, v.y * w, v.z * w, v.w * w);
}

// out = relu(l2norm(0.5*h*(1+dinv^2) + 0.5*agg)); one warp per node, float2 per lane
__global__ void k_post(const float* __restrict__ h, const float* __restrict__ agg,
                       float* out) {
    int node = blockIdx.x * 8 + (threadIdx.x >> 5);
    int lane = threadIdx.x & 31;
    if (node >= NN) return;
    float di = g_dinv[node];
    float hw = 0.5f * (1.0f + di * di);   // self part: 0.5*h + 0.5*h*dinv^2
    const float2* hp = (const float2*)(h + (size_t)node * DH);
    const float2* ap = (const float2*)(agg + (size_t)node * DH);
    float2 a = hp[lane];
    float2 g = ap[lane];
    float vx = hw * a.x + 0.5f * g.x;
    float vy = hw * a.y + 0.5f * g.y;
    float s = vx * vx + vy * vy;
#pragma unroll
    for (int o = 16; o; o >>= 1) s += __shfl_xor_sync(0xFFFFFFFFu, s, o);
    float inv = 1.0f / fmaxf(sqrtf(s), 1e-12f);
    float2 o2;
    o2.x = fmaxf(vx * inv, 0.0f);
    o2.y = fmaxf(vy * inv, 0.0f);
    ((float2*)(out + (size_t)node * DH))[lane] = o2;
}

// ---------------- launch ----------------

extern "C" void kernel_launch(void* const* d_in, const int* in_sizes, int n_in,
                              void* d_out, int out_size) {
    const float* x  = (const float*)d_in[0];
    const int*   ei = (const int*)d_in[1];
    const float* W0 = (const float*)d_in[2];
    const float* b0 = (const float*)d_in[3];
    const float* W1 = (const float*)d_in[4];
    const float* b1 = (const float*)d_in[5];
    const float* W2 = (const float*)d_in[6];
    const float* b2 = (const float*)d_in[7];
    float* out = (float*)d_out;

    const int* src = ei;
    const int* dst = ei + NE;

    float *pA, *pB;
    cudaGetSymbolAddress((void**)&pA, g_bufA);
    cudaGetSymbolAddress((void**)&pB, g_bufB);

    const int T = 256;
    int gN  = (NN + T - 1) / T;
    int gE  = (NE + T - 1) / T;
    int gZ  = (NN * DH / 4 + T - 1) / T;
    int gP  = (NE * 16 + T - 1) / T;
    int gG  = (NN + 63) / 64;
    int gPost = (NN + 7) / 8;

    // degree / dinv (recomputed each call: deterministic, no caching)
    k_deg_init<<<gN, T>>>();
    k_deg_accum<<<gE, T>>>(dst);
    k_dinv<<<gN, T>>>();

    // layer 0
    k_gemm<DIN><<<gG, T>>>(x, W0, b0, pA);
    k_zero<<<gZ, T>>>(pB);
    k_prop<<<gP, T>>>(src, dst, pA, pB);
    k_post<<<gPost, T>>>(pA, pB, pA);

    // layer 1
    k_gemm<DH><<<gG, T>>>(pA, W1, b1, pB);
    k_zero<<<gZ, T>>>(pA);
    k_prop<<<gP, T>>>(src, dst, pB, pA);
    k_post<<<gPost, T>>>(pB, pA, pB);

    // final linear
    k_gemm<DH><<<gG, T>>>(pB, W2, b2, out);
}

// round 4
// speedup vs baseline: 1.8476x; 1.6270x over previous
#include <cuda_runtime.h>
#include <math.h>

#define NN 100000
#define NE 1600000
#define DIN 128
#define DH 64

// Scratch (allocation-free: __device__ globals)
__device__ float g_bufA[NN * DH];
__device__ float g_bufB[NN * DH];
__device__ float g_deg[NN];
__device__ float g_dinv[NN];

// ---------------- degree prep ----------------

__global__ void k_deg_init() {
    int i = blockIdx.x * blockDim.x + threadIdx.x;
    if (i < NN) g_deg[i] = 1.0f;  // self-loop
}

__global__ void k_deg_accum(const int* __restrict__ dst) {
    int e = blockIdx.x * blockDim.x + threadIdx.x;
    if (e < NE) atomicAdd(&g_deg[dst[e]], 1.0f);
}

__global__ void k_dinv() {
    int i = blockIdx.x * blockDim.x + threadIdx.x;
    if (i < NN) g_dinv[i] = rsqrtf(g_deg[i]);
}

// ---------------- GEMM: H[n,64] = X[n,K] @ W[64,K]^T + b ----------------
// 4x4 register tile per thread: per k, 2x LDS.128 + 16 FMA.
// Block: 256 threads -> 64 nodes x 64 cols. K processed in 64-wide chunks.

#define KC 64
#define SPAD 68   // smem row stride (floats): 16B aligned, staggers banks

template <int K>
__global__ void __launch_bounds__(256) k_gemm(const float* __restrict__ X,
                                              const float* __restrict__ W,
                                              const float* __restrict__ B,
                                              float* __restrict__ H) {
    __shared__ float sW[KC][SPAD];   // sW[k][j]  (transposed W chunk)
    __shared__ float sX[KC][SPAD];   // sX[k][nn] (transposed X chunk)
    int tid = threadIdx.x;
    int c = tid & 15;      // col quad -> cols [4c, 4c+3]
    int r = tid >> 4;      // node quad -> nodes [4r, 4r+3]
    int n0 = blockIdx.x * 64;

    float acc[4][4];
#pragma unroll
    for (int i = 0; i < 4; i++)
#pragma unroll
        for (int j = 0; j < 4; j++) acc[i][j] = 0.0f;

#pragma unroll
    for (int kb = 0; kb < K; kb += KC) {
        __syncthreads();
        // stage W chunk: coalesced global read, transposed STS
#pragma unroll
        for (int i = tid; i < 64 * KC; i += 256) {
            int j = i >> 6;
            int k = i & 63;
            sW[k][j] = W[j * K + kb + k];
        }
        // stage X chunk: float4 global reads, transposed scalar STS
#pragma unroll
        for (int i = tid; i < 64 * (KC / 4); i += 256) {
            int kq = i & 15;
            int nn = i >> 4;
            int node = n0 + nn;
            float4 v = (node < NN)
                ? *(const float4*)(X + (size_t)node * K + kb + kq * 4)
                : make_float4(0.f, 0.f, 0.f, 0.f);
            sX[kq * 4 + 0][nn] = v.x;
            sX[kq * 4 + 1][nn] = v.y;
            sX[kq * 4 + 2][nn] = v.z;
            sX[kq * 4 + 3][nn] = v.w;
        }
        __syncthreads();

#pragma unroll 16
        for (int k = 0; k < KC; k++) {
            float4 w  = *(const float4*)(&sW[k][c * 4]);
            float4 xv = *(const float4*)(&sX[k][r * 4]);
            acc[0][0] = fmaf(xv.x, w.x, acc[0][0]);
            acc[0][1] = fmaf(xv.x, w.y, acc[0][1]);
            acc[0][2] = fmaf(xv.x, w.z, acc[0][2]);
            acc[0][3] = fmaf(xv.x, w.w, acc[0][3]);
            acc[1][0] = fmaf(xv.y, w.x, acc[1][0]);
            acc[1][1] = fmaf(xv.y, w.y, acc[1][1]);
            acc[1][2] = fmaf(xv.y, w.z, acc[1][2]);
            acc[1][3] = fmaf(xv.y, w.w, acc[1][3]);
            acc[2][0] = fmaf(xv.z, w.x, acc[2][0]);
            acc[2][1] = fmaf(xv.z, w.y, acc[2][1]);
            acc[2][2] = fmaf(xv.z, w.z, acc[2][2]);
            acc[2][3] = fmaf(xv.z, w.w, acc[2][3]);
            acc[3][0] = fmaf(xv.w, w.x, acc[3][0]);
            acc[3][1] = fmaf(xv.w, w.y, acc[3][1]);
            acc[3][2] = fmaf(xv.w, w.z, acc[3][2]);
            acc[3][3] = fmaf(xv.w, w.w, acc[3][3]);
        }
    }

    float4 bias = *(const float4*)(B + c * 4);
#pragma unroll
    for (int i = 0; i < 4; i++) {
        int node = n0 + r * 4 + i;
        if (node < NN) {
            float4 o;
            o.x = acc[i][0] + bias.x;
            o.y = acc[i][1] + bias.y;
            o.z = acc[i][2] + bias.z;
            o.w = acc[i][3] + bias.w;
            *(float4*)(H + (size_t)node * DH + c * 4) = o;
        }
    }
}

// ---------------- propagation ----------------

// zero the accumulator (write-only; self-loop folded into k_post)
__global__ void k_zero(float* __restrict__ agg) {
    int i = blockIdx.x * blockDim.x + threadIdx.x;
    if (i < NN * DH / 4) ((float4*)agg)[i] = make_float4(0.f, 0.f, 0.f, 0.f);
}

// vectorized global reduction: one 16B atomic add instead of 4 scalar ones
__device__ __forceinline__ void red_add_v4(float* p, float a, float b, float c, float d) {
    asm volatile("red.global.add.v4.f32 [%0], {%1, %2, %3, %4};"
                 :: "l"(p), "f"(a), "f"(b), "f"(c), "f"(d) : "memory");
}

// agg[dst] += dinv[src]*dinv[dst] * h[src]   (16 threads per edge, one red.v4 each)
__global__ void k_prop(const int* __restrict__ src, const int* __restrict__ dst,
                       const float* __restrict__ h, float* agg) {
    int idx = blockIdx.x * blockDim.x + threadIdx.x;
    int e = idx >> 4;
    if (e >= NE) return;
    int c = (idx & 15) << 2;
    int s = src[e];
    int d = dst[e];
    float w = g_dinv[s] * g_dinv[d];
    float4 v = *(const float4*)(h + (size_t)s * DH + c);
    float* o = agg + (size_t)d * DH + c;
    red_add_v4(o, v.x * w, v.y * w, v.z * w, v.w * w);
}

// out = relu(l2norm(0.5*h*(1+dinv^2) + 0.5*agg)); one warp per node, float2 per lane
__global__ void k_post(const float* __restrict__ h, const float* __restrict__ agg,
                       float* out) {
    int node = blockIdx.x * 8 + (threadIdx.x >> 5);
    int lane = threadIdx.x & 31;
    if (node >= NN) return;
    float di = g_dinv[node];
    float hw = 0.5f * (1.0f + di * di);   // self part: 0.5*h + 0.5*h*dinv^2
    const float2* hp = (const float2*)(h + (size_t)node * DH);
    const float2* ap = (const float2*)(agg + (size_t)node * DH);
    float2 a = hp[lane];
    float2 g = ap[lane];
    float vx = hw * a.x + 0.5f * g.x;
    float vy = hw * a.y + 0.5f * g.y;
    float s = vx * vx + vy * vy;
#pragma unroll
    for (int o = 16; o; o >>= 1) s += __shfl_xor_sync(0xFFFFFFFFu, s, o);
    float inv = 1.0f / fmaxf(sqrtf(s), 1e-12f);
    float2 o2;
    o2.x = fmaxf(vx * inv, 0.0f);
    o2.y = fmaxf(vy * inv, 0.0f);
    ((float2*)(out + (size_t)node * DH))[lane] = o2;
}

// ---------------- launch ----------------

extern "C" void kernel_launch(void* const* d_in, const int* in_sizes, int n_in,
                              void* d_out, int out_size) {
    const float* x  = (const float*)d_in[0];
    const int*   ei = (const int*)d_in[1];
    const float* W0 = (const float*)d_in[2];
    const float* b0 = (const float*)d_in[3];
    const float* W1 = (const float*)d_in[4];
    const float* b1 = (const float*)d_in[5];
    const float* W2 = (const float*)d_in[6];
    const float* b2 = (const float*)d_in[7];
    float* out = (float*)d_out;

    const int* src = ei;
    const int* dst = ei + NE;

    float *pA, *pB;
    cudaGetSymbolAddress((void**)&pA, g_bufA);
    cudaGetSymbolAddress((void**)&pB, g_bufB);

    const int T = 256;
    int gN  = (NN + T - 1) / T;
    int gE  = (NE + T - 1) / T;
    int gZ  = (NN * DH / 4 + T - 1) / T;
    int gP  = (NE * 16 + T - 1) / T;
    int gG  = (NN + 63) / 64;
    int gPost = (NN + 7) / 8;

    // degree / dinv (recomputed each call: deterministic, no caching)
    k_deg_init<<<gN, T>>>();
    k_deg_accum<<<gE, T>>>(dst);
    k_dinv<<<gN, T>>>();

    // layer 0
    k_gemm<DIN><<<gG, T>>>(x, W0, b0, pA);
    k_zero<<<gZ, T>>>(pB);
    k_prop<<<gP, T>>>(src, dst, pA, pB);
    k_post<<<gPost, T>>>(pA, pB, pA);

    // layer 1
    k_gemm<DH><<<gG, T>>>(pA, W1, b1, pB);
    k_zero<<<gZ, T>>>(pA);
    k_prop<<<gP, T>>>(src, dst, pB, pA);
    k_post<<<gPost, T>>>(pB, pA, pB);

    // final linear
    k_gemm<DH><<<gG, T>>>(pB, W2, b2, out);
}

// round 5
// speedup vs baseline: 2.6153x; 1.4155x over previous
#include <cuda_runtime.h>
#include <math.h>

#define NN 100000
#define NE 1600000
#define DIN 128
#define DH 64
#define SCAN_T 256
#define SCAN_BLK 1024                 // items per scan block
#define NB ((NN + SCAN_BLK - 1) / SCAN_BLK)   // 98

// Scratch (allocation-free: __device__ globals)
__device__ float g_bufA[NN * DH];
__device__ float g_bufB[NN * DH];
__device__ float g_dinv[NN];
__device__ int   g_counts[NN];
__device__ int   g_row_start[NN];
__device__ int   g_row_next[NN];
__device__ int   g_csr_col[NE];
__device__ int   g_blocksums[128];

// ---------------- CSR build: histogram -> scan -> scatter ----------------

__global__ void k_zero_counts() {
    int i = blockIdx.x * blockDim.x + threadIdx.x;
    if (i < NN) g_counts[i] = 0;
}

__global__ void k_count(const int* __restrict__ dst) {
    int e = blockIdx.x * blockDim.x + threadIdx.x;
    if (e < NE) atomicAdd(&g_counts[dst[e]], 1);
}

// per-block exclusive scan over 1024 counts; emit block sums
__global__ void k_scan_blocks() {
    __shared__ int sh[SCAN_T];
    int t = threadIdx.x;
    int base = blockIdx.x * SCAN_BLK + t * 4;
    int v[4], s = 0;
#pragma unroll
    for (int j = 0; j < 4; j++) {
        int idx = base + j;
        v[j] = (idx < NN) ? g_counts[idx] : 0;
        s += v[j];
    }
    sh[t] = s;
    __syncthreads();
    for (int off = 1; off < SCAN_T; off <<= 1) {
        int x = (t >= off) ? sh[t - off] : 0;
        __syncthreads();
        sh[t] += x;
        __syncthreads();
    }
    int run = sh[t] - s;   // exclusive prefix for this thread
    if (t == SCAN_T - 1) g_blocksums[blockIdx.x] = sh[t];
#pragma unroll
    for (int j = 0; j < 4; j++) {
        int idx = base + j;
        if (idx < NN) g_row_start[idx] = run;
        run += v[j];
    }
}

// single-block exclusive scan of the 98 block sums
__global__ void k_scan_tops() {
    __shared__ int sh[128];
    int t = threadIdx.x;   // 128 threads
    int v = (t < NB) ? g_blocksums[t] : 0;
    sh[t] = v;
    __syncthreads();
    for (int off = 1; off < 128; off <<= 1) {
        int x = (t >= off) ? sh[t - off] : 0;
        __syncthreads();
        sh[t] += x;
        __syncthreads();
    }
    if (t < NB) g_blocksums[t] = sh[t] - v;
}

// add block offsets, init scatter cursors, compute dinv
__global__ void k_finalize() {
    int i = blockIdx.x * blockDim.x + threadIdx.x;
    if (i < NN) {
        int rs = g_row_start[i] + g_blocksums[i >> 10];
        g_row_start[i] = rs;
        g_row_next[i] = rs;
        g_dinv[i] = rsqrtf((float)g_counts[i] + 1.0f);   // +1 self-loop
    }
}

__global__ void k_fill(const int* __restrict__ src, const int* __restrict__ dst) {
    int e = blockIdx.x * blockDim.x + threadIdx.x;
    if (e < NE) {
        int p = atomicAdd(&g_row_next[dst[e]], 1);
        g_csr_col[p] = src[e];
    }
}

// ---------------- GEMM: H[n,64] = X[n,K] @ W[64,K]^T + b ----------------
// 4x4 register tile per thread: per k, 2x LDS.128 + 16 FMA.

#define KC 64
#define SPAD 68

template <int K>
__global__ void __launch_bounds__(256) k_gemm(const float* __restrict__ X,
                                              const float* __restrict__ W,
                                              const float* __restrict__ B,
                                              float* __restrict__ H) {
    __shared__ float sW[KC][SPAD];
    __shared__ float sX[KC][SPAD];
    int tid = threadIdx.x;
    int c = tid & 15;
    int r = tid >> 4;
    int n0 = blockIdx.x * 64;

    float acc[4][4];
#pragma unroll
    for (int i = 0; i < 4; i++)
#pragma unroll
        for (int j = 0; j < 4; j++) acc[i][j] = 0.0f;

#pragma unroll
    for (int kb = 0; kb < K; kb += KC) {
        __syncthreads();
#pragma unroll
        for (int i = tid; i < 64 * KC; i += 256) {
            int j = i >> 6;
            int k = i & 63;
            sW[k][j] = W[j * K + kb + k];
        }
#pragma unroll
        for (int i = tid; i < 64 * (KC / 4); i += 256) {
            int kq = i & 15;
            int nn = i >> 4;
            int node = n0 + nn;
            float4 v = (node < NN)
                ? *(const float4*)(X + (size_t)node * K + kb + kq * 4)
                : make_float4(0.f, 0.f, 0.f, 0.f);
            sX[kq * 4 + 0][nn] = v.x;
            sX[kq * 4 + 1][nn] = v.y;
            sX[kq * 4 + 2][nn] = v.z;
            sX[kq * 4 + 3][nn] = v.w;
        }
        __syncthreads();

#pragma unroll 16
        for (int k = 0; k < KC; k++) {
            float4 w  = *(const float4*)(&sW[k][c * 4]);
            float4 xv = *(const float4*)(&sX[k][r * 4]);
            acc[0][0] = fmaf(xv.x, w.x, acc[0][0]);
            acc[0][1] = fmaf(xv.x, w.y, acc[0][1]);
            acc[0][2] = fmaf(xv.x, w.z, acc[0][2]);
            acc[0][3] = fmaf(xv.x, w.w, acc[0][3]);
            acc[1][0] = fmaf(xv.y, w.x, acc[1][0]);
            acc[1][1] = fmaf(xv.y, w.y, acc[1][1]);
            acc[1][2] = fmaf(xv.y, w.z, acc[1][2]);
            acc[1][3] = fmaf(xv.y, w.w, acc[1][3]);
            acc[2][0] = fmaf(xv.z, w.x, acc[2][0]);
            acc[2][1] = fmaf(xv.z, w.y, acc[2][1]);
            acc[2][2] = fmaf(xv.z, w.z, acc[2][2]);
            acc[2][3] = fmaf(xv.z, w.w, acc[2][3]);
            acc[3][0] = fmaf(xv.w, w.x, acc[3][0]);
            acc[3][1] = fmaf(xv.w, w.y, acc[3][1]);
            acc[3][2] = fmaf(xv.w, w.z, acc[3][2]);
            acc[3][3] = fmaf(xv.w, w.w, acc[3][3]);
        }
    }

    float4 bias = *(const float4*)(B + c * 4);
#pragma unroll
    for (int i = 0; i < 4; i++) {
        int node = n0 + r * 4 + i;
        if (node < NN) {
            float4 o;
            o.x = acc[i][0] + bias.x;
            o.y = acc[i][1] + bias.y;
            o.z = acc[i][2] + bias.z;
            o.w = acc[i][3] + bias.w;
            *(float4*)(H + (size_t)node * DH + c * 4) = o;
        }
    }
}

// ---------------- fused pull propagation + l2norm + relu ----------------
// One warp per dst node; lane owns 2 columns. Register accumulation, no atomics.
// out = relu(l2norm((0.5+0.5*dinv_d^2)*h_d + 0.5*dinv_d * sum_s dinv_s*h_s))

__global__ void __launch_bounds__(256) k_pull(const float* __restrict__ h,
                                              float* __restrict__ out) {
    int node = blockIdx.x * 8 + (threadIdx.x >> 5);
    int lane = threadIdx.x & 31;
    if (node >= NN) return;

    int start = g_row_start[node];
    int cnt   = g_counts[node];
    const int* cp = g_csr_col + start;

    float ax = 0.f, ay = 0.f;
    int i = 0;
    for (; i + 2 <= cnt; i += 2) {
        int s0 = __ldg(cp + i);
        int s1 = __ldg(cp + i + 1);
        float w0 = g_dinv[s0];
        float w1 = g_dinv[s1];
        float2 v0 = *(const float2*)(h + (size_t)s0 * DH + lane * 2);
        float2 v1 = *(const float2*)(h + (size_t)s1 * DH + lane * 2);
        ax = fmaf(w0, v0.x, ax); ay = fmaf(w0, v0.y, ay);
        ax = fmaf(w1, v1.x, ax); ay = fmaf(w1, v1.y, ay);
    }
    if (i < cnt) {
        int s0 = __ldg(cp + i);
        float w0 = g_dinv[s0];
        float2 v0 = *(const float2*)(h + (size_t)s0 * DH + lane * 2);
        ax = fmaf(w0, v0.x, ax); ay = fmaf(w0, v0.y, ay);
    }

    float di = g_dinv[node];
    float hw = 0.5f * (1.0f + di * di);
    float hd = 0.5f * di;
    float2 hv = *(const float2*)(h + (size_t)node * DH + lane * 2);
    float vx = fmaf(hw, hv.x, hd * ax);
    float vy = fmaf(hw, hv.y, hd * ay);

    float s = vx * vx + vy * vy;
#pragma unroll
    for (int o = 16; o; o >>= 1) s += __shfl_xor_sync(0xFFFFFFFFu, s, o);
    float inv = 1.0f / fmaxf(sqrtf(s), 1e-12f);
    float2 o2;
    o2.x = fmaxf(vx * inv, 0.0f);
    o2.y = fmaxf(vy * inv, 0.0f);
    ((float2*)(out + (size_t)node * DH))[lane] = o2;
}

// ---------------- launch ----------------

extern "C" void kernel_launch(void* const* d_in, const int* in_sizes, int n_in,
                              void* d_out, int out_size) {
    const float* x  = (const float*)d_in[0];
    const int*   ei = (const int*)d_in[1];
    const float* W0 = (const float*)d_in[2];
    const float* b0 = (const float*)d_in[3];
    const float* W1 = (const float*)d_in[4];
    const float* b1 = (const float*)d_in[5];
    const float* W2 = (const float*)d_in[6];
    const float* b2 = (const float*)d_in[7];
    float* out = (float*)d_out;

    const int* src = ei;
    const int* dst = ei + NE;

    float *pA, *pB;
    cudaGetSymbolAddress((void**)&pA, g_bufA);
    cudaGetSymbolAddress((void**)&pB, g_bufB);

    const int T = 256;
    int gN  = (NN + T - 1) / T;
    int gE  = (NE + T - 1) / T;
    int gG  = (NN + 63) / 64;
    int gPull = (NN + 7) / 8;

    // CSR build (recomputed each call: deterministic work, no caching)
    k_zero_counts<<<gN, T>>>();
    k_count<<<gE, T>>>(dst);
    k_scan_blocks<<<NB, SCAN_T>>>();
    k_scan_tops<<<1, 128>>>();
    k_finalize<<<gN, T>>>();
    k_fill<<<gE, T>>>(src, dst);

    // layer 0
    k_gemm<DIN><<<gG, T>>>(x, W0, b0, pA);
    k_pull<<<gPull, T>>>(pA, pB);

    // layer 1
    k_gemm<DH><<<gG, T>>>(pB, W1, b1, pA);
    k_pull<<<gPull, T>>>(pA, pB);

    // final linear
    k_gemm<DH><<<gG, T>>>(pB, W2, b2, out);
}

// round 6
// speedup vs baseline: 2.8439x; 1.0874x over previous
#include <cuda_runtime.h>
#include <math.h>

#define NN 100000
#define NE 1600000
#define DIN 128
#define DH 64
#define SCAN_T 256
#define SCAN_BLK 1024                 // items per scan block
#define NB ((NN + SCAN_BLK - 1) / SCAN_BLK)   // 98

// Scratch (allocation-free: __device__ globals)
__device__ float g_bufA[NN * DH];
__device__ float g_bufB[NN * DH];
__device__ float g_dinv[NN];
__device__ int   g_counts[NN];
__device__ int   g_row_start[NN];
__device__ int   g_row_next[NN];
__device__ int   g_csr_col[NE];
__device__ int   g_blocksums[128];

// ---------------- CSR build: histogram -> scan -> scatter ----------------

__global__ void k_zero_counts() {
    int i = blockIdx.x * blockDim.x + threadIdx.x;
    if (i < NN) g_counts[i] = 0;
}

__global__ void k_count(const int* __restrict__ dst) {
    int e = blockIdx.x * blockDim.x + threadIdx.x;
    if (e < NE) atomicAdd(&g_counts[dst[e]], 1);
}

// per-block exclusive scan over 1024 counts; emit block sums
__global__ void k_scan_blocks() {
    __shared__ int sh[SCAN_T];
    int t = threadIdx.x;
    int base = blockIdx.x * SCAN_BLK + t * 4;
    int v[4], s = 0;
#pragma unroll
    for (int j = 0; j < 4; j++) {
        int idx = base + j;
        v[j] = (idx < NN) ? g_counts[idx] : 0;
        s += v[j];
    }
    sh[t] = s;
    __syncthreads();
    for (int off = 1; off < SCAN_T; off <<= 1) {
        int x = (t >= off) ? sh[t - off] : 0;
        __syncthreads();
        sh[t] += x;
        __syncthreads();
    }
    int run = sh[t] - s;   // exclusive prefix for this thread
    if (t == SCAN_T - 1) g_blocksums[blockIdx.x] = sh[t];
#pragma unroll
    for (int j = 0; j < 4; j++) {
        int idx = base + j;
        if (idx < NN) g_row_start[idx] = run;
        run += v[j];
    }
}

// finalize: every block redundantly scans the 98 block sums in smem (cheap),
// then adds block offsets, inits scatter cursors, computes dinv.
__global__ void k_finalize() {
    __shared__ int sh[128];
    __shared__ int ex[128];
    int t = threadIdx.x;   // 256 threads
    int v = 0;
    if (t < 128) {
        v = (t < NB) ? g_blocksums[t] : 0;
        sh[t] = v;
    }
    __syncthreads();
    for (int off = 1; off < 128; off <<= 1) {
        int x = (t < 128 && t >= off) ? sh[t - off] : 0;
        __syncthreads();
        if (t < 128) sh[t] += x;
        __syncthreads();
    }
    if (t < 128) ex[t] = sh[t] - v;   // exclusive
    __syncthreads();

    int i = blockIdx.x * blockDim.x + t;
    if (i < NN) {
        int rs = g_row_start[i] + ex[i >> 10];
        g_row_start[i] = rs;
        g_row_next[i] = rs;
        g_dinv[i] = rsqrtf((float)g_counts[i] + 1.0f);   // +1 self-loop
    }
}

__global__ void k_fill(const int* __restrict__ src, const int* __restrict__ dst) {
    int e = blockIdx.x * blockDim.x + threadIdx.x;
    if (e < NE) {
        int p = atomicAdd(&g_row_next[dst[e]], 1);
        g_csr_col[p] = src[e];
    }
}

// ---------------- GEMM: H[n,64] = X[n,K] @ W[64,K]^T + b ----------------
// 8x4 register tile per thread: per k, 3x LDS.128 + 32 FMA.
// Block: 256 threads -> 128 nodes x 64 cols. K in 32-wide chunks.

#define KC 32
#define WPAD 68    // sW row stride
#define XPAD 132   // sX row stride (128 nodes + 4)

template <int K>
__global__ void __launch_bounds__(256) k_gemm(const float* __restrict__ X,
                                              const float* __restrict__ W,
                                              const float* __restrict__ B,
                                              float* __restrict__ H) {
    __shared__ float sW[KC][WPAD];    // sW[k][j]
    __shared__ float sX[KC][XPAD];    // sX[k][nn]
    int tid = threadIdx.x;
    int c = tid & 15;      // col quad -> cols [4c, 4c+3]
    int r = tid >> 4;      // node octet -> nodes [8r, 8r+7]
    int n0 = blockIdx.x * 128;

    float acc[8][4];
#pragma unroll
    for (int i = 0; i < 8; i++)
#pragma unroll
        for (int j = 0; j < 4; j++) acc[i][j] = 0.0f;

#pragma unroll
    for (int kb = 0; kb < K; kb += KC) {
        __syncthreads();
        // stage W chunk: 64 j x 32 k, coalesced read, transposed STS
#pragma unroll
        for (int i = tid; i < 64 * KC; i += 256) {
            int j = i >> 5;
            int k = i & 31;
            sW[k][j] = W[j * K + kb + k];
        }
        // stage X chunk: 128 nodes x 32 k via float4, transposed STS
#pragma unroll
        for (int i = tid; i < 128 * (KC / 4); i += 256) {
            int kq = i & 7;
            int nn = i >> 3;
            int node = n0 + nn;
            float4 v = (node < NN)
                ? *(const float4*)(X + (size_t)node * K + kb + kq * 4)
                : make_float4(0.f, 0.f, 0.f, 0.f);
            sX[kq * 4 + 0][nn] = v.x;
            sX[kq * 4 + 1][nn] = v.y;
            sX[kq * 4 + 2][nn] = v.z;
            sX[kq * 4 + 3][nn] = v.w;
        }
        __syncthreads();

#pragma unroll
        for (int k = 0; k < KC; k++) {
            float4 w  = *(const float4*)(&sW[k][c * 4]);
            float4 x0 = *(const float4*)(&sX[k][r * 8]);
            float4 x1 = *(const float4*)(&sX[k][r * 8 + 4]);
            float xs[8] = {x0.x, x0.y, x0.z, x0.w, x1.x, x1.y, x1.z, x1.w};
#pragma unroll
            for (int i = 0; i < 8; i++) {
                acc[i][0] = fmaf(xs[i], w.x, acc[i][0]);
                acc[i][1] = fmaf(xs[i], w.y, acc[i][1]);
                acc[i][2] = fmaf(xs[i], w.z, acc[i][2]);
                acc[i][3] = fmaf(xs[i], w.w, acc[i][3]);
            }
        }
    }

    float4 bias = *(const float4*)(B + c * 4);
#pragma unroll
    for (int i = 0; i < 8; i++) {
        int node = n0 + r * 8 + i;
        if (node < NN) {
            float4 o;
            o.x = acc[i][0] + bias.x;
            o.y = acc[i][1] + bias.y;
            o.z = acc[i][2] + bias.z;
            o.w = acc[i][3] + bias.w;
            *(float4*)(H + (size_t)node * DH + c * 4) = o;
        }
    }
}

// ---------------- fused pull propagation + l2norm + relu ----------------
// One warp per dst node; lane owns 2 columns. Register accumulation, no atomics.

__global__ void __launch_bounds__(256) k_pull(const float* __restrict__ h,
                                              float* __restrict__ out) {
    int node = blockIdx.x * 8 + (threadIdx.x >> 5);
    int lane = threadIdx.x & 31;
    if (node >= NN) return;

    int start = g_row_start[node];
    int cnt   = g_counts[node];
    const int* cp = g_csr_col + start;

    float ax = 0.f, ay = 0.f;
    int i = 0;
    for (; i + 4 <= cnt; i += 4) {
        int s0 = __ldg(cp + i);
        int s1 = __ldg(cp + i + 1);
        int s2 = __ldg(cp + i + 2);
        int s3 = __ldg(cp + i + 3);
        float w0 = g_dinv[s0];
        float w1 = g_dinv[s1];
        float w2 = g_dinv[s2];
        float w3 = g_dinv[s3];
        float2 v0 = *(const float2*)(h + (size_t)s0 * DH + lane * 2);
        float2 v1 = *(const float2*)(h + (size_t)s1 * DH + lane * 2);
        float2 v2 = *(const float2*)(h + (size_t)s2 * DH + lane * 2);
        float2 v3 = *(const float2*)(h + (size_t)s3 * DH + lane * 2);
        ax = fmaf(w0, v0.x, ax); ay = fmaf(w0, v0.y, ay);
        ax = fmaf(w1, v1.x, ax); ay = fmaf(w1, v1.y, ay);
        ax = fmaf(w2, v2.x, ax); ay = fmaf(w2, v2.y, ay);
        ax = fmaf(w3, v3.x, ax); ay = fmaf(w3, v3.y, ay);
    }
    for (; i < cnt; i++) {
        int s0 = __ldg(cp + i);
        float w0 = g_dinv[s0];
        float2 v0 = *(const float2*)(h + (size_t)s0 * DH + lane * 2);
        ax = fmaf(w0, v0.x, ax); ay = fmaf(w0, v0.y, ay);
    }

    float di = g_dinv[node];
    float hw = 0.5f * (1.0f + di * di);
    float hd = 0.5f * di;
    float2 hv = *(const float2*)(h + (size_t)node * DH + lane * 2);
    float vx = fmaf(hw, hv.x, hd * ax);
    float vy = fmaf(hw, hv.y, hd * ay);

    float s = vx * vx + vy * vy;
#pragma unroll
    for (int o = 16; o; o >>= 1) s += __shfl_xor_sync(0xFFFFFFFFu, s, o);
    float inv = 1.0f / fmaxf(sqrtf(s), 1e-12f);
    float2 o2;
    o2.x = fmaxf(vx * inv, 0.0f);
    o2.y = fmaxf(vy * inv, 0.0f);
    ((float2*)(out + (size_t)node * DH))[lane] = o2;
}

// ---------------- launch ----------------

extern "C" void kernel_launch(void* const* d_in, const int* in_sizes, int n_in,
                              void* d_out, int out_size) {
    const float* x  = (const float*)d_in[0];
    const int*   ei = (const int*)d_in[1];
    const float* W0 = (const float*)d_in[2];
    const float* b0 = (const float*)d_in[3];
    const float* W1 = (const float*)d_in[4];
    const float* b1 = (const float*)d_in[5];
    const float* W2 = (const float*)d_in[6];
    const float* b2 = (const float*)d_in[7];
    float* out = (float*)d_out;

    const int* src = ei;
    const int* dst = ei + NE;

    float *pA, *pB;
    cudaGetSymbolAddress((void**)&pA, g_bufA);
    cudaGetSymbolAddress((void**)&pB, g_bufB);

    const int T = 256;
    int gN  = (NN + T - 1) / T;
    int gE  = (NE + T - 1) / T;
    int gG  = (NN + 127) / 128;
    int gPull = (NN + 7) / 8;

    // CSR build (recomputed each call: deterministic work, no caching)
    k_zero_counts<<<gN, T>>>();
    k_count<<<gE, T>>>(dst);
    k_scan_blocks<<<NB, SCAN_T>>>();
    k_finalize<<<gN, T>>>();
    k_fill<<<gE, T>>>(src, dst);

    // layer 0
    k_gemm<DIN><<<gG, T>>>(x, W0, b0, pA);
    k_pull<<<gPull, T>>>(pA, pB);

    // layer 1
    k_gemm<DH><<<gG, T>>>(pB, W1, b1, pA);
    k_pull<<<gPull, T>>>(pA, pB);

    // final linear
    k_gemm<DH><<<gG, T>>>(pB, W2, b2, out);
}

// round 7
// speedup vs baseline: 3.0269x; 1.0644x over previous
#include <cuda_runtime.h>
#include <math.h>

#define NN 100000
#define NE 1600000
#define DIN 128
#define DH 64
#define SCAN_T 256
#define SCAN_BLK 1024                 // items per scan block
#define NB ((NN + SCAN_BLK - 1) / SCAN_BLK)   // 98

// Scratch (allocation-free: __device__ globals)
__device__ float g_bufA[NN * DH];
__device__ float g_bufB[NN * DH];
__device__ float g_dinv[NN];
__device__ int   g_counts[NN];
__device__ int   g_row_start[NN];
__device__ int   g_row_next[NN];
__device__ int   g_csr_col[NE];
__device__ int   g_blocksums[128];

// ---------------- CSR build: histogram -> scan -> scatter ----------------

__global__ void k_zero_counts() {
    int i = blockIdx.x * blockDim.x + threadIdx.x;
    if (i < NN) g_counts[i] = 0;
}

__global__ void k_count(const int* __restrict__ dst) {
    int e = blockIdx.x * blockDim.x + threadIdx.x;
    if (e < NE) atomicAdd(&g_counts[dst[e]], 1);
}

// per-block exclusive scan over 1024 counts; emit block sums
__global__ void k_scan_blocks() {
    __shared__ int sh[SCAN_T];
    int t = threadIdx.x;
    int base = blockIdx.x * SCAN_BLK + t * 4;
    int v[4], s = 0;
#pragma unroll
    for (int j = 0; j < 4; j++) {
        int idx = base + j;
        v[j] = (idx < NN) ? g_counts[idx] : 0;
        s += v[j];
    }
    sh[t] = s;
    __syncthreads();
    for (int off = 1; off < SCAN_T; off <<= 1) {
        int x = (t >= off) ? sh[t - off] : 0;
        __syncthreads();
        sh[t] += x;
        __syncthreads();
    }
    int run = sh[t] - s;   // exclusive prefix for this thread
    if (t == SCAN_T - 1) g_blocksums[blockIdx.x] = sh[t];
#pragma unroll
    for (int j = 0; j < 4; j++) {
        int idx = base + j;
        if (idx < NN) g_row_start[idx] = run;
        run += v[j];
    }
}

// finalize: every block redundantly scans the 98 block sums in smem (cheap),
// then adds block offsets, inits scatter cursors, computes dinv.
__global__ void k_finalize() {
    __shared__ int sh[128];
    __shared__ int ex[128];
    int t = threadIdx.x;   // 256 threads
    int v = 0;
    if (t < 128) {
        v = (t < NB) ? g_blocksums[t] : 0;
        sh[t] = v;
    }
    __syncthreads();
    for (int off = 1; off < 128; off <<= 1) {
        int x = (t < 128 && t >= off) ? sh[t - off] : 0;
        __syncthreads();
        if (t < 128) sh[t] += x;
        __syncthreads();
    }
    if (t < 128) ex[t] = sh[t] - v;   // exclusive
    __syncthreads();

    int i = blockIdx.x * blockDim.x + t;
    if (i < NN) {
        int rs = g_row_start[i] + ex[i >> 10];
        g_row_start[i] = rs;
        g_row_next[i] = rs;
        g_dinv[i] = rsqrtf((float)g_counts[i] + 1.0f);   // +1 self-loop
    }
}

__global__ void k_fill(const int* __restrict__ src, const int* __restrict__ dst) {
    int e = blockIdx.x * blockDim.x + threadIdx.x;
    if (e < NE) {
        int p = atomicAdd(&g_row_next[dst[e]], 1);
        g_csr_col[p] = src[e];
    }
}

// ---------------- GEMM: H[n,64] = X[n,K] @ W[64,K]^T + b ----------------
// 8x4 register tile per thread: per k, 3x LDS.128 + 32 FMA.
// Block: 256 threads -> 128 nodes x 64 cols. K in 32-wide chunks.

#define KC 32
#define WPAD 68    // sW row stride
#define XPAD 132   // sX row stride (128 nodes + 4)

template <int K>
__global__ void __launch_bounds__(256) k_gemm(const float* __restrict__ X,
                                              const float* __restrict__ W,
                                              const float* __restrict__ B,
                                              float* __restrict__ H) {
    __shared__ float sW[KC][WPAD];    // sW[k][j]
    __shared__ float sX[KC][XPAD];    // sX[k][nn]
    int tid = threadIdx.x;
    int c = tid & 15;      // col quad -> cols [4c, 4c+3]
    int r = tid >> 4;      // node octet -> nodes [8r, 8r+7]
    int n0 = blockIdx.x * 128;

    float acc[8][4];
#pragma unroll
    for (int i = 0; i < 8; i++)
#pragma unroll
        for (int j = 0; j < 4; j++) acc[i][j] = 0.0f;

#pragma unroll
    for (int kb = 0; kb < K; kb += KC) {
        __syncthreads();
        // stage W chunk: 64 j x 32 k, coalesced read, transposed STS
#pragma unroll
        for (int i = tid; i < 64 * KC; i += 256) {
            int j = i >> 5;
            int k = i & 31;
            sW[k][j] = W[j * K + kb + k];
        }
        // stage X chunk: 128 nodes x 32 k via float4, transposed STS
#pragma unroll
        for (int i = tid; i < 128 * (KC / 4); i += 256) {
            int kq = i & 7;
            int nn = i >> 3;
            int node = n0 + nn;
            float4 v = (node < NN)
                ? *(const float4*)(X + (size_t)node * K + kb + kq * 4)
                : make_float4(0.f, 0.f, 0.f, 0.f);
            sX[kq * 4 + 0][nn] = v.x;
            sX[kq * 4 + 1][nn] = v.y;
            sX[kq * 4 + 2][nn] = v.z;
            sX[kq * 4 + 3][nn] = v.w;
        }
        __syncthreads();

#pragma unroll
        for (int k = 0; k < KC; k++) {
            float4 w  = *(const float4*)(&sW[k][c * 4]);
            float4 x0 = *(const float4*)(&sX[k][r * 8]);
            float4 x1 = *(const float4*)(&sX[k][r * 8 + 4]);
            float xs[8] = {x0.x, x0.y, x0.z, x0.w, x1.x, x1.y, x1.z, x1.w};
#pragma unroll
            for (int i = 0; i < 8; i++) {
                acc[i][0] = fmaf(xs[i], w.x, acc[i][0]);
                acc[i][1] = fmaf(xs[i], w.y, acc[i][1]);
                acc[i][2] = fmaf(xs[i], w.z, acc[i][2]);
                acc[i][3] = fmaf(xs[i], w.w, acc[i][3]);
            }
        }
    }

    float4 bias = *(const float4*)(B + c * 4);
#pragma unroll
    for (int i = 0; i < 8; i++) {
        int node = n0 + r * 8 + i;
        if (node < NN) {
            float4 o;
            o.x = acc[i][0] + bias.x;
            o.y = acc[i][1] + bias.y;
            o.z = acc[i][2] + bias.z;
            o.w = acc[i][3] + bias.w;
            *(float4*)(H + (size_t)node * DH + c * 4) = o;
        }
    }
}

// ---------------- fused pull propagation + l2norm + relu ----------------
// One warp per dst node; lane owns 2 columns. Register accumulation, no atomics.

__global__ void __launch_bounds__(256) k_pull(const float* __restrict__ h,
                                              float* __restrict__ out) {
    int node = blockIdx.x * 8 + (threadIdx.x >> 5);
    int lane = threadIdx.x & 31;
    if (node >= NN) return;

    int start = g_row_start[node];
    int cnt   = g_counts[node];
    const int* cp = g_csr_col + start;

    float ax = 0.f, ay = 0.f;
    int i = 0;
    for (; i + 4 <= cnt; i += 4) {
        int s0 = __ldg(cp + i);
        int s1 = __ldg(cp + i + 1);
        int s2 = __ldg(cp + i + 2);
        int s3 = __ldg(cp + i + 3);
        float w0 = g_dinv[s0];
        float w1 = g_dinv[s1];
        float w2 = g_dinv[s2];
        float w3 = g_dinv[s3];
        float2 v0 = *(const float2*)(h + (size_t)s0 * DH + lane * 2);
        float2 v1 = *(const float2*)(h + (size_t)s1 * DH + lane * 2);
        float2 v2 = *(const float2*)(h + (size_t)s2 * DH + lane * 2);
        float2 v3 = *(const float2*)(h + (size_t)s3 * DH + lane * 2);
        ax = fmaf(w0, v0.x, ax); ay = fmaf(w0, v0.y, ay);
        ax = fmaf(w1, v1.x, ax); ay = fmaf(w1, v1.y, ay);
        ax = fmaf(w2, v2.x, ax); ay = fmaf(w2, v2.y, ay);
        ax = fmaf(w3, v3.x, ax); ay = fmaf(w3, v3.y, ay);
    }
    for (; i < cnt; i++) {
        int s0 = __ldg(cp + i);
        float w0 = g_dinv[s0];
        float2 v0 = *(const float2*)(h + (size_t)s0 * DH + lane * 2);
        ax = fmaf(w0, v0.x, ax); ay = fmaf(w0, v0.y, ay);
    }

    float di = g_dinv[node];
    float hw = 0.5f * (1.0f + di * di);
    float hd = 0.5f * di;
    float2 hv = *(const float2*)(h + (size_t)node * DH + lane * 2);
    float vx = fmaf(hw, hv.x, hd * ax);
    float vy = fmaf(hw, hv.y, hd * ay);

    float s = vx * vx + vy * vy;
#pragma unroll
    for (int o = 16; o; o >>= 1) s += __shfl_xor_sync(0xFFFFFFFFu, s, o);
    float inv = 1.0f / fmaxf(sqrtf(s), 1e-12f);
    float2 o2;
    o2.x = fmaxf(vx * inv, 0.0f);
    o2.y = fmaxf(vy * inv, 0.0f);
    ((float2*)(out + (size_t)node * DH))[lane] = o2;
}

// ---------------- launch ----------------

extern "C" void kernel_launch(void* const* d_in, const int* in_sizes, int n_in,
                              void* d_out, int out_size) {
    const float* x  = (const float*)d_in[0];
    const int*   ei = (const int*)d_in[1];
    const float* W0 = (const float*)d_in[2];
    const float* b0 = (const float*)d_in[3];
    const float* W1 = (const float*)d_in[4];
    const float* b1 = (const float*)d_in[5];
    const float* W2 = (const float*)d_in[6];
    const float* b2 = (const float*)d_in[7];
    float* out = (float*)d_out;

    const int* src = ei;
    const int* dst = ei + NE;

    float *pA, *pB;
    cudaGetSymbolAddress((void**)&pA, g_bufA);
    cudaGetSymbolAddress((void**)&pB, g_bufB);

    const int T = 256;
    int gN  = (NN + T - 1) / T;
    int gE  = (NE + T - 1) / T;
    int gG  = (NN + 127) / 128;
    int gPull = (NN + 7) / 8;

    // Lazily-created side stream + events (host resources only; reused across
    // calls so capture sees identical structure every time).
    static cudaStream_t s2 = 0;
    static cudaEvent_t evFork = 0, evJoin = 0;
    static int streamOK = -1;
    if (streamOK < 0) {
        streamOK = (cudaStreamCreateWithFlags(&s2, cudaStreamNonBlocking) == cudaSuccess &&
                    cudaEventCreateWithFlags(&evFork, cudaEventDisableTiming) == cudaSuccess &&
                    cudaEventCreateWithFlags(&evJoin, cudaEventDisableTiming) == cudaSuccess)
                   ? 1 : 0;
    }

    if (streamOK) {
        // fork: CSR build on s2, concurrent with layer-0 GEMM on stream 0
        cudaEventRecord(evFork, 0);
        cudaStreamWaitEvent(s2, evFork, 0);

        k_zero_counts<<<gN, T, 0, s2>>>();
        k_count<<<gE, T, 0, s2>>>(dst);
        k_scan_blocks<<<NB, SCAN_T, 0, s2>>>();
        k_finalize<<<gN, T, 0, s2>>>();
        k_fill<<<gE, T, 0, s2>>>(src, dst);
        cudaEventRecord(evJoin, s2);

        k_gemm<DIN><<<gG, T>>>(x, W0, b0, pA);

        // join: pull needs both CSR and gemm0 output
        cudaStreamWaitEvent(0, evJoin, 0);
    } else {
        // fallback: fully serial on default stream
        k_zero_counts<<<gN, T>>>();
        k_count<<<gE, T>>>(dst);
        k_scan_blocks<<<NB, SCAN_T>>>();
        k_finalize<<<gN, T>>>();
        k_fill<<<gE, T>>>(src, dst);
        k_gemm<DIN><<<gG, T>>>(x, W0, b0, pA);
    }

    k_pull<<<gPull, T>>>(pA, pB);

    // layer 1
    k_gemm<DH><<<gG, T>>>(pB, W1, b1, pA);
    k_pull<<<gPull, T>>>(pA, pB);

    // final linear
    k_gemm<DH><<<gG, T>>>(pB, W2, b2, out);
}